// round 13
// baseline (speedup 1.0000x reference)
#include <cuda_runtime.h>
#include <cuda_bf16.h>
#include <math.h>
#include <stdint.h>

// Problem constants
#define BATCH 1024
#define ZDIM  512
#define ADIM  8
#define AH    64
#define ZH    512
#define NNEG  100
#define NCOLS 1123
#define LDSIM 1152

// split-bf16 storage: [hi | lo], segment-walked 3x in the GEMM
#define KP2   1024          // 2*512
#define KPG2  128           // 2*64

// ---------------- device scratch ----------------
__device__ float d_g[BATCH * ZH];
__device__ float d_zwb[BATCH * ZH];
__device__ float d_u[BATCH * ZDIM];
__device__ float d_simmat[BATCH * LDSIM];
__device__ float d_negp[4][BATCH * 128];      // k-quarter partials of neg_sim
__device__ float d_base[BATCH];               // (z[b]+b2).zn[b]
__device__ float d_rowlog[BATCH];
__device__ int   d_rowcnt[BATCH];

__device__ __nv_bfloat16 d_Af[BATCH * KP2];    // z_next'  [h|l]
__device__ __nv_bfloat16 d_Az[BATCH * KP2];    // z'
__device__ __nv_bfloat16 d_Ag[BATCH * KPG2];   // ha0'
__device__ __nv_bfloat16 d_Bf[1536 * KP2];     // rows 0:1024 znh', 1024:1536 W2'
__device__ __nv_bfloat16 d_Bw1[512 * KP2];     // W1[0:512]^T'
__device__ __nv_bfloat16 d_Bg[512 * KPG2];     // W1[512:576]^T'

// ---------------- split helper ----------------
__device__ __forceinline__ void split4(float4 v, __nv_bfloat16* hb, __nv_bfloat16* lb) {
    const float* c = &v.x;
#pragma unroll
    for (int j = 0; j < 4; j++) {
        __nv_bfloat16 h = __float2bfloat16(c[j]);
        hb[j] = h;
        lb[j] = __float2bfloat16(c[j] - __bfloat162float(h));
    }
}
#define ST8(p, a) (*reinterpret_cast<uint2*>(p) = *reinterpret_cast<const uint2*>(a))

// ---------------- conversions + ha0 + base, one launch, grid 2248 ----------------
__global__ void __launch_bounds__(256)
k_conv(const float* __restrict__ zn, const float* __restrict__ z,
       const float* __restrict__ znh, const float* __restrict__ W2,
       const float* __restrict__ W1,
       const float* __restrict__ actions, const float* __restrict__ Wa,
       const float* __restrict__ ba, const float* __restrict__ b2,
       __nv_bfloat16* __restrict__ Af, __nv_bfloat16* __restrict__ Az,
       __nv_bfloat16* __restrict__ Bf, __nv_bfloat16* __restrict__ Bw1,
       __nv_bfloat16* __restrict__ Bg, __nv_bfloat16* __restrict__ Ag,
       float* __restrict__ basev) {
    __shared__ float tile[64][65];
    int bid = blockIdx.x, tid = threadIdx.x;
    __align__(8) __nv_bfloat16 hb[4], lb[4];

    if (bid < 1536) {
        // element-wise: Af <- z_next | Az <- z | Bf[0:1024] <- znh
        const float* src; __nv_bfloat16* dst;
        if (bid < 512)       { src = zn;  dst = Af; }
        else if (bid < 1024) { src = z;   dst = Az; bid -= 512; }
        else                 { src = znh; dst = Bf; bid -= 1024; }
        int e4 = bid * 256 + tid;
        int m = e4 >> 7, k = (e4 & 127) * 4;
        split4(((const float4*)src)[e4], hb, lb);
        __nv_bfloat16* r = dst + (size_t)m * KP2 + k;
        ST8(r, hb); ST8(r + 512, lb);
    } else if (bid < 1792) {
        // W2 -> Bf rows 1024:1536
        int e4 = (bid - 1536) * 256 + tid;
        int n = e4 >> 7, k = (e4 & 127) * 4;
        split4(((const float4*)W2)[e4], hb, lb);
        __nv_bfloat16* r = Bf + (size_t)(1024 + n) * KP2 + k;
        ST8(r, hb); ST8(r + 512, lb);
    } else if (bid < 1856) {
        // W1[0:512]^T -> Bw1, 64x64 tile transpose
        int t = bid - 1792;
        int tr = t >> 3, tc = t & 7;          // k-tile, n-tile
#pragma unroll
        for (int it = 0; it < 4; it++) {
            int idx = it * 256 + tid;
            int rk = idx >> 4, c4 = idx & 15;
            float4 v = *(const float4*)(W1 + (size_t)(tr * 64 + rk) * ZH + tc * 64 + c4 * 4);
            tile[rk][c4 * 4 + 0] = v.x; tile[rk][c4 * 4 + 1] = v.y;
            tile[rk][c4 * 4 + 2] = v.z; tile[rk][c4 * 4 + 3] = v.w;
        }
        __syncthreads();
#pragma unroll
        for (int it = 0; it < 4; it++) {
            int idx = it * 256 + tid;
            int nr = idx >> 4, k4 = idx & 15;
            float4 v = make_float4(tile[k4 * 4 + 0][nr], tile[k4 * 4 + 1][nr],
                                   tile[k4 * 4 + 2][nr], tile[k4 * 4 + 3][nr]);
            split4(v, hb, lb);
            int k = tr * 64 + k4 * 4;
            __nv_bfloat16* r = Bw1 + (size_t)(tc * 64 + nr) * KP2 + k;
            ST8(r, hb); ST8(r + 512, lb);
        }
    } else if (bid < 1864) {
        // W1[512:576]^T -> Bg
        int t = bid - 1856;                   // n-tile 0..7
#pragma unroll
        for (int it = 0; it < 4; it++) {
            int idx = it * 256 + tid;
            int rk = idx >> 4, c4 = idx & 15;
            float4 v = *(const float4*)(W1 + (size_t)(512 + rk) * ZH + t * 64 + c4 * 4);
            tile[rk][c4 * 4 + 0] = v.x; tile[rk][c4 * 4 + 1] = v.y;
            tile[rk][c4 * 4 + 2] = v.z; tile[rk][c4 * 4 + 3] = v.w;
        }
        __syncthreads();
#pragma unroll
        for (int it = 0; it < 4; it++) {
            int idx = it * 256 + tid;
            int nr = idx >> 4, k4 = idx & 15;
            float4 v = make_float4(tile[k4 * 4 + 0][nr], tile[k4 * 4 + 1][nr],
                                   tile[k4 * 4 + 2][nr], tile[k4 * 4 + 3][nr]);
            split4(v, hb, lb);
            int k = k4 * 4;
            __nv_bfloat16* r = Bg + (size_t)(t * 64 + nr) * KPG2 + k;
            ST8(r, hb); ST8(r + 64, lb);
        }
    } else if (bid < 2120) {
        // ha0 = relu(actions@Wa+ba), split -> Ag
        int idx = (bid - 1864) * 256 + tid;
        int b = idx >> 6, h = idx & 63;
        float s = ba[h];
#pragma unroll
        for (int a = 0; a < ADIM; a++)
            s += actions[b * ADIM + a] * Wa[a * AH + h];
        s = fmaxf(s, 0.f);
        __nv_bfloat16 hi = __float2bfloat16(s);
        __nv_bfloat16 lo = __float2bfloat16(s - __bfloat162float(hi));
        __nv_bfloat16* r = Ag + (size_t)b * KPG2;
        r[h] = hi; r[64 + h] = lo;
    } else {
        // base[b] = (z[b]+b2) . zn[b], 8 rows per block (warp per row)
        int b0 = (bid - 2120) * 8;
        int w = tid >> 5, lane = tid & 31;
        int b = b0 + w;
        const float4* z4 = (const float4*)(z + (size_t)b * ZDIM);
        const float4* zn4 = (const float4*)(zn + (size_t)b * ZDIM);
        const float4* b24 = (const float4*)b2;
        float bp = 0.f;
#pragma unroll
        for (int k4 = lane; k4 < 128; k4 += 32) {
            float4 a = z4[k4], c = zn4[k4], d = b24[k4];
            bp += (a.x + d.x) * c.x + (a.y + d.y) * c.y
                + (a.z + d.z) * c.z + (a.w + d.w) * c.w;
        }
#pragma unroll
        for (int o = 16; o; o >>= 1) bp += __shfl_xor_sync(0xffffffffu, bp, o);
        if (lane == 0) basev[b] = bp;
    }
}

// ---------------- HMMA GEMM: 128x128 tiles, grid 128 (1 CTA/SM), job chaining ------
// bid<96: fused tile; bid in [96,128): zwb tile. bids 0..31 additionally run a
// light g-tile (T=6) as a second job -> 54-chunk critical path, no second wave.
#define SM_PITCH 40
#define STAGE_ELEMS (2 * 128 * SM_PITCH)     // A-half + B-half per stage (bf16 elems)
#define MMA_DSMEM (3 * STAGE_ELEMS * 2)      // bytes = 61440

__device__ __forceinline__ void mma16816(float* d, const uint32_t* a, const uint32_t* b) {
    asm volatile(
        "mma.sync.aligned.m16n8k16.row.col.f32.bf16.bf16.f32 "
        "{%0,%1,%2,%3}, {%4,%5,%6,%7}, {%8,%9}, {%0,%1,%2,%3};"
        : "+f"(d[0]), "+f"(d[1]), "+f"(d[2]), "+f"(d[3])
        : "r"(a[0]), "r"(a[1]), "r"(a[2]), "r"(a[3]), "r"(b[0]), "r"(b[1]));
}
__device__ __forceinline__ void cpa16(const void* s, const void* gp) {
    uint32_t sa;
    asm("{ .reg .u64 t; cvta.to.shared.u64 t, %1; cvt.u32.u64 %0, t; }" : "=r"(sa) : "l"(s));
    asm volatile("cp.async.cg.shared.global [%0], [%1], 16;\n" :: "r"(sa), "l"(gp));
}
__device__ __forceinline__ void ldsm4(uint32_t* r, const __nv_bfloat16* p) {
    uint32_t sa;
    asm("{ .reg .u64 t; cvta.to.shared.u64 t, %1; cvt.u32.u64 %0, t; }" : "=r"(sa) : "l"(p));
    asm volatile("ldmatrix.sync.aligned.m8n8.x4.shared.b16 {%0,%1,%2,%3}, [%4];"
                 : "=r"(r[0]), "=r"(r[1]), "=r"(r[2]), "=r"(r[3]) : "r"(sa));
}

__global__ void __launch_bounds__(256, 1)
k_mma(const __nv_bfloat16* __restrict__ Af, const __nv_bfloat16* __restrict__ Az,
      const __nv_bfloat16* __restrict__ Ag, const __nv_bfloat16* __restrict__ Bf,
      const __nv_bfloat16* __restrict__ Bw1, const __nv_bfloat16* __restrict__ Bg,
      const float* __restrict__ b1,
      float* __restrict__ zwb, float* __restrict__ g,
      float* __restrict__ u, float* __restrict__ simmat) {
    extern __shared__ __align__(16) __nv_bfloat16 dsm[];
#define AS(s, r, c) dsm[(s) * STAGE_ELEMS + (r) * SM_PITCH + (c)]
#define BS(s, r, c) dsm[(s) * STAGE_ELEMS + 128 * SM_PITCH + (r) * SM_PITCH + (c)]

    const int tid = threadIdx.x;          // 256
    const int lane = tid & 31, warp = tid >> 5;
    const int grp = lane >> 2, qid = lane & 3;
    const int wm = warp >> 2, wn = warp & 3;   // 2 x 4 warp grid
    const int bid = blockIdx.x;

    // ldmatrix lane addressing
    const int arow0 = wm * 64 + (lane & 7) + ((lane >> 3) & 1) * 8;
    const int akoff = ((lane >> 4) & 1) * 8;
    const int brow0 = wn * 32 + (lane & 7) + ((lane >> 4) & 1) * 8;
    const int bkoff = ((lane >> 3) & 1) * 8;

    const int njobs = (bid < 32) ? 2 : 1;

    for (int job = 0; job < njobs; job++) {
        // ---- job setup ----
        const __nv_bfloat16 *Aseg, *Bseg;
        float* Cseg; const float* bias = nullptr;
        int ldk, T, m0, ldc, ccol0, sshift, half;
        if (job == 0) {
            if (bid < 96) {
                int mt = bid / 12, nt = bid % 12;
                m0 = mt * 128; Aseg = Af; ldk = KP2; T = 48; sshift = 4; half = 512;
                Bseg = Bf + (size_t)nt * 128 * KP2;
                if (nt < 8) { Cseg = simmat; ldc = LDSIM; ccol0 = nt * 128; }
                else        { Cseg = u;      ldc = ZDIM;  ccol0 = (nt - 8) * 128; }
            } else {
                int t = bid - 96; int mt = t >> 2, nt = t & 3;
                m0 = mt * 128; Aseg = Az; ldk = KP2; T = 48; sshift = 4; half = 512;
                Bseg = Bw1 + (size_t)nt * 128 * KP2;
                Cseg = zwb; ldc = ZH; ccol0 = nt * 128; bias = b1;
            }
        } else {
            int t = bid; int mt = t >> 2, nt = t & 3;
            m0 = mt * 128; Aseg = Ag; ldk = KPG2; T = 6; sshift = 1; half = 64;
            Bseg = Bg + (size_t)nt * 128 * KPG2;
            Cseg = g; ldc = ZH; ccol0 = nt * 128;
        }

        float acc[4][4][4];
#pragma unroll
        for (int i = 0; i < 4; i++)
#pragma unroll
            for (int j = 0; j < 4; j++)
#pragma unroll
                for (int q = 0; q < 4; q++) acc[i][j][q] = 0.f;

        auto load_chunk = [&](int t, int st) {
            int sgm = t >> sshift, tt = t - (sgm << sshift);
            const __nv_bfloat16* Ac = Aseg + (sgm == 2 ? half : 0) + tt * 32;
            const __nv_bfloat16* Bc = Bseg + (sgm == 1 ? half : 0) + tt * 32;
#pragma unroll
            for (int it = 0; it < 2; it++) {
                int idx = it * 256 + tid;
                int row = idx >> 2, sg = (idx & 3) * 8;
                cpa16(&AS(st, row, sg), Ac + (size_t)(m0 + row) * ldk + sg);
            }
#pragma unroll
            for (int it = 0; it < 2; it++) {
                int idx = it * 256 + tid;
                int row = idx >> 2, sg = (idx & 3) * 8;
                cpa16(&BS(st, row, sg), Bc + (size_t)row * ldk + sg);
            }
            asm volatile("cp.async.commit_group;\n" ::: "memory");
        };

        if (job > 0) __syncthreads();    // smem reuse barrier between jobs
        load_chunk(0, 0);
        load_chunk(1, 1);

        for (int t = 0; t < T; t++) {
            const int s = t % 3;
            if (t + 1 < T) asm volatile("cp.async.wait_group 1;\n" ::: "memory");
            else           asm volatile("cp.async.wait_group 0;\n" ::: "memory");
            __syncthreads();
            if (t + 2 < T) load_chunk(t + 2, (t + 2) % 3);

#pragma unroll
            for (int ks = 0; ks < 2; ks++) {
                uint32_t afr[4][4], bt0[4], bt1[4];
                const int akol = ks * 16 + akoff;
                const int bkol = ks * 16 + bkoff;
#pragma unroll
                for (int mi = 0; mi < 4; mi++)
                    ldsm4(afr[mi], &AS(s, arow0 + mi * 16, akol));
                ldsm4(bt0, &BS(s, brow0, bkol));
                ldsm4(bt1, &BS(s, brow0 + 16, bkol));
                uint32_t bfr[4][2] = {{bt0[0], bt0[1]}, {bt0[2], bt0[3]},
                                      {bt1[0], bt1[1]}, {bt1[2], bt1[3]}};
#pragma unroll
                for (int mi = 0; mi < 4; mi++)
#pragma unroll
                    for (int ni = 0; ni < 4; ni++)
                        mma16816(acc[mi][ni], afr[mi], bfr[ni]);
            }
        }

        // ---- epilogue ----
#pragma unroll
        for (int mi = 0; mi < 4; mi++) {
            int m = m0 + wm * 64 + mi * 16 + grp;
#pragma unroll
            for (int ni = 0; ni < 4; ni++) {
                int n = ccol0 + wn * 32 + ni * 8 + qid * 2;
                float bx = 0.f, by = 0.f;
                if (bias) { bx = bias[n]; by = bias[n + 1]; }
                *(float2*)&Cseg[(size_t)m * ldc + n] =
                    make_float2(acc[mi][ni][0] + bx, acc[mi][ni][1] + by);
                *(float2*)&Cseg[(size_t)(m + 8) * ldc + n] =
                    make_float2(acc[mi][ni][2] + bx, acc[mi][ni][3] + by);
            }
        }
    }
#undef AS
#undef BS
}

// ---------------- neg_sim: k-quarter per block, grid 1024 (proven R9) --------
#define KC 64
__global__ void __launch_bounds__(256, 5)
k_neg(const float* __restrict__ zwb, const float* __restrict__ g,
      const float* __restrict__ u, float* __restrict__ negp) {
    const int tile  = blockIdx.x >> 3;
    const int ihalf = (blockIdx.x >> 2) & 1;
    const int kq    = blockIdx.x & 3;
    const int b0 = tile * 8;
    const int ibase = 1 + ihalf * 49;
    const int icount = 49 + ihalf;
    const int tid = threadIdx.x, w = tid >> 5, lane = tid & 31;
    const int b = b0 + w;

    __shared__ float zc[8][KC];
    __shared__ float uc[8][KC];
    __shared__ float gs[KC][73];

    float acc1 = 0.f, acc2 = 0.f;
    const int r1 = w + lane, r2 = r1 + 32;

#pragma unroll 1
    for (int j = 0; j < 2; j++) {
        const int kc4 = kq * 32 + j * 16;
        __syncthreads();
        {
            int idx = tid & 127;
            int row = idx >> 4, k4 = idx & 15;
            const float4* src = (tid < 128) ? (const float4*)zwb : (const float4*)u;
            float4 v = src[(size_t)(b0 + row) * 128 + kc4 + k4];
            float* dst = (tid < 128) ? &zc[row][k4 * 4] : &uc[row][k4 * 4];
            *(float4*)dst = v;
        }
        for (int idx = tid; idx < 57 * 16; idx += 256) {
            int k4 = idx / 57, row = idx - k4 * 57;
            int gr = (b0 + ibase + row) & (BATCH - 1);
            float4 v = ((const float4*)g)[(size_t)gr * 128 + kc4 + k4];
            gs[k4 * 4 + 0][row] = v.x;
            gs[k4 * 4 + 1][row] = v.y;
            gs[k4 * 4 + 2][row] = v.z;
            gs[k4 * 4 + 3][row] = v.w;
        }
        __syncthreads();
#pragma unroll
        for (int k = 0; k < KC; k += 4) {
            float4 zv4 = *(const float4*)&zc[w][k];
            float4 uv4 = *(const float4*)&uc[w][k];
#pragma unroll
            for (int kk = 0; kk < 4; kk++) {
                float zv = (&zv4.x)[kk], uv = (&uv4.x)[kk];
                acc1 += fmaxf(zv + gs[k + kk][r1], 0.f) * uv;
                acc2 += fmaxf(zv + gs[k + kk][r2], 0.f) * uv;
            }
        }
    }

    float* orow = negp + (size_t)kq * (BATCH * 128) + (size_t)b * 128;
    orow[ibase + lane] = acc1;
    if (lane + 32 < icount)
        orow[ibase + lane + 32] = acc2;
}

// ---------------- per-row softmax + rank count (base precomputed, float4) ----------
__global__ void __launch_bounds__(256)
k_row(const float* __restrict__ simmat, const float* __restrict__ negp,
      const float* __restrict__ basev,
      float* __restrict__ rowlog, int* __restrict__ rowcnt) {
    int b = blockIdx.x;
    int tid = threadIdx.x;   // 256
    const float* row = simmat + (size_t)b * LDSIM;
    const float* pq = negp + (size_t)b * 128;

    const float base = basev[b];
    const float s = row[b];

    float lv[5];
    {
        float4 v4 = ((const float4*)row)[tid];
        lv[0] = v4.x; lv[1] = v4.y; lv[2] = v4.z; lv[3] = v4.w;
    }
    const bool has_neg = (tid < NNEG - 1);
    if (has_neg) {
        int i = tid + 1;
        lv[4] = base + pq[i] + pq[BATCH * 128 + i]
                     + pq[2 * BATCH * 128 + i] + pq[3 * BATCH * 128 + i];
    }
    float mx = lv[0];
#pragma unroll
    for (int q = 1; q < 4; q++) mx = fmaxf(mx, lv[q]);
    if (has_neg) mx = fmaxf(mx, lv[4]);
    float se = 0.f;
#pragma unroll
    for (int q = 0; q < 4; q++) se += __expf((lv[q] - mx) * 10.f);
    if (has_neg) se += __expf((lv[4] - mx) * 10.f);
    int cnt = 0;
    int j0 = tid * 4;
#pragma unroll
    for (int q = 0; q < 4; q++)
        cnt += (lv[q] > s) || (lv[q] == s && (j0 + q) < b);
    if (has_neg) cnt += (lv[4] > s);

#pragma unroll
    for (int o = 16; o; o >>= 1) {
        float om = __shfl_xor_sync(0xffffffffu, mx, o);
        float os = __shfl_xor_sync(0xffffffffu, se, o);
        cnt += __shfl_xor_sync(0xffffffffu, cnt, o);
        float nm = fmaxf(mx, om);
        se = se * __expf((mx - nm) * 10.f) + os * __expf((om - nm) * 10.f);
        mx = nm;
    }
    __shared__ float smx[8], ssm[8];
    __shared__ int scn[8];
    if ((tid & 31) == 0) { smx[tid >> 5] = mx; ssm[tid >> 5] = se; scn[tid >> 5] = cnt; }
    __syncthreads();
    if (tid == 0) {
        float m = smx[0], t = ssm[0]; int c = scn[0];
#pragma unroll
        for (int wv = 1; wv < 8; wv++) {
            float om = smx[wv], os = ssm[wv];
            float nm = fmaxf(m, om);
            t = t * __expf((m - nm) * 10.f) + os * __expf((om - nm) * 10.f);
            m = nm;
            c += scn[wv];
        }
        rowlog[b] = (s - m) * 10.f - logf(t);
        rowcnt[b] = c;
    }
}

// ---------------- final reduction ----------------
__global__ void k_final(const float* __restrict__ rowlog,
                        const int* __restrict__ rowcnt,
                        float* __restrict__ out) {
    int tid = threadIdx.x;  // 1024
    float lg = rowlog[tid];
    int c = rowcnt[tid];
    float a1 = (c < 1) ? 1.f : 0.f;
    float a3 = (c < 3) ? 1.f : 0.f;
    float a10 = (c < 10) ? 1.f : 0.f;

    __shared__ float s0[32], s1[32], s2[32], s3[32];
#pragma unroll
    for (int o = 16; o; o >>= 1) {
        lg  += __shfl_xor_sync(0xffffffffu, lg, o);
        a1  += __shfl_xor_sync(0xffffffffu, a1, o);
        a3  += __shfl_xor_sync(0xffffffffu, a3, o);
        a10 += __shfl_xor_sync(0xffffffffu, a10, o);
    }
    int wid = tid >> 5, lane = tid & 31;
    if (lane == 0) { s0[wid] = lg; s1[wid] = a1; s2[wid] = a3; s3[wid] = a10; }
    __syncthreads();
    if (wid == 0) {
        float v0 = s0[lane], v1 = s1[lane], v2 = s2[lane], v3 = s3[lane];
#pragma unroll
        for (int o = 16; o; o >>= 1) {
            v0 += __shfl_xor_sync(0xffffffffu, v0, o);
            v1 += __shfl_xor_sync(0xffffffffu, v1, o);
            v2 += __shfl_xor_sync(0xffffffffu, v2, o);
            v3 += __shfl_xor_sync(0xffffffffu, v3, o);
        }
        if (lane == 0) {
            out[0] = -v0 / (float)BATCH;
            out[1] = v1 / (float)BATCH;
            out[2] = v2 / (float)BATCH;
            out[3] = v3 / (float)BATCH;
        }
    }
}

// ---------------- launch ----------------
extern "C" void kernel_launch(void* const* d_in, const int* in_sizes, int n_in,
                              void* d_out, int out_size) {
    const float* z          = (const float*)d_in[0];
    const float* z_next     = (const float*)d_in[1];
    const float* z_next_hat = (const float*)d_in[2];
    const float* actions    = (const float*)d_in[3];
    const float* Wa         = (const float*)d_in[4];
    const float* ba         = (const float*)d_in[5];
    const float* W1         = (const float*)d_in[6];
    const float* b1         = (const float*)d_in[7];
    const float* W2         = (const float*)d_in[8];
    const float* b2         = (const float*)d_in[9];
    float* out = (float*)d_out;

    float *g, *zwb, *u, *simmat, *negp, *basev, *rowlog; int* rowcnt;
    __nv_bfloat16 *Af, *Az, *Ag, *Bf, *Bw1, *Bg;
    cudaGetSymbolAddress((void**)&g, d_g);
    cudaGetSymbolAddress((void**)&zwb, d_zwb);
    cudaGetSymbolAddress((void**)&u, d_u);
    cudaGetSymbolAddress((void**)&simmat, d_simmat);
    cudaGetSymbolAddress((void**)&negp, d_negp);
    cudaGetSymbolAddress((void**)&basev, d_base);
    cudaGetSymbolAddress((void**)&rowlog, d_rowlog);
    cudaGetSymbolAddress((void**)&rowcnt, d_rowcnt);
    cudaGetSymbolAddress((void**)&Af, d_Af);
    cudaGetSymbolAddress((void**)&Az, d_Az);
    cudaGetSymbolAddress((void**)&Ag, d_Ag);
    cudaGetSymbolAddress((void**)&Bf, d_Bf);
    cudaGetSymbolAddress((void**)&Bw1, d_Bw1);
    cudaGetSymbolAddress((void**)&Bg, d_Bg);

    cudaFuncSetAttribute(k_mma, cudaFuncAttributeMaxDynamicSharedMemorySize, MMA_DSMEM);

    // 1. conversions + W1 transposes + ha0 + base dots
    k_conv<<<2248, 256>>>(z_next, z, z_next_hat, W2, W1, actions, Wa, ba, b2,
                          Af, Az, Bf, Bw1, Bg, Ag, basev);
    // 2. all GEMMs (sim, u, zwb, g) — grid 128, one CTA/SM, in-kernel job chaining
    k_mma<<<128, 256, MMA_DSMEM>>>(Af, Az, Ag, Bf, Bw1, Bg, b1, zwb, g, u, simmat);
    // 3. neg_sim k-quarter partials
    k_neg<<<1024, 256>>>(zwb, g, u, negp);
    // 4. per-row softmax + rank counts
    k_row<<<BATCH, 256>>>(simmat, negp, basev, rowlog, rowcnt);
    // 5. final outputs
    k_final<<<1, 1024>>>(rowlog, rowcnt, out);
}

// round 14
// speedup vs baseline: 1.1326x; 1.1326x over previous
#include <cuda_runtime.h>
#include <cuda_bf16.h>
#include <math.h>
#include <stdint.h>

// Problem constants
#define BATCH 1024
#define ZDIM  512
#define ADIM  8
#define AH    64
#define ZH    512
#define NNEG  100
#define NCOLS 1123
#define LDSIM 1152

// split-bf16 storage: [hi | lo], segment-walked 3x in the GEMM
#define KP2   1024          // 2*512
#define KPG2  128           // 2*64

// ---------------- device scratch ----------------
__device__ float d_g[BATCH * ZH];
__device__ float d_zwb[BATCH * ZH];
__device__ float d_u[BATCH * ZDIM];
__device__ float d_simmat[BATCH * LDSIM];
__device__ float d_negp[4][BATCH * 128];      // k-quarter partials of neg_sim
__device__ float d_base[BATCH];               // (z[b]+b2).zn[b]
__device__ float d_rowlog[BATCH];
__device__ int   d_rowcnt[BATCH];

__device__ __nv_bfloat16 d_Af[BATCH * KP2];    // z_next'  [h|l]
__device__ __nv_bfloat16 d_Az[BATCH * KP2];    // z'
__device__ __nv_bfloat16 d_Ag[BATCH * KPG2];   // ha0'
__device__ __nv_bfloat16 d_Bf[1536 * KP2];     // rows 0:1024 znh', 1024:1536 W2'
__device__ __nv_bfloat16 d_Bw1[512 * KP2];     // W1[0:512]^T'
__device__ __nv_bfloat16 d_Bg[512 * KPG2];     // W1[512:576]^T'

// ---------------- split helper ----------------
__device__ __forceinline__ void split4(float4 v, __nv_bfloat16* hb, __nv_bfloat16* lb) {
    const float* c = &v.x;
#pragma unroll
    for (int j = 0; j < 4; j++) {
        __nv_bfloat16 h = __float2bfloat16(c[j]);
        hb[j] = h;
        lb[j] = __float2bfloat16(c[j] - __bfloat162float(h));
    }
}
#define ST8(p, a) (*reinterpret_cast<uint2*>(p) = *reinterpret_cast<const uint2*>(a))

// ---------------- conversions + ha0 + base, one launch, grid 2248 ----------------
__global__ void __launch_bounds__(256)
k_conv(const float* __restrict__ zn, const float* __restrict__ z,
       const float* __restrict__ znh, const float* __restrict__ W2,
       const float* __restrict__ W1,
       const float* __restrict__ actions, const float* __restrict__ Wa,
       const float* __restrict__ ba, const float* __restrict__ b2,
       __nv_bfloat16* __restrict__ Af, __nv_bfloat16* __restrict__ Az,
       __nv_bfloat16* __restrict__ Bf, __nv_bfloat16* __restrict__ Bw1,
       __nv_bfloat16* __restrict__ Bg, __nv_bfloat16* __restrict__ Ag,
       float* __restrict__ basev) {
    __shared__ float tile[64][65];
    int bid = blockIdx.x, tid = threadIdx.x;
    __align__(8) __nv_bfloat16 hb[4], lb[4];

    if (bid < 1536) {
        // element-wise: Af <- z_next | Az <- z | Bf[0:1024] <- znh
        const float* src; __nv_bfloat16* dst;
        if (bid < 512)       { src = zn;  dst = Af; }
        else if (bid < 1024) { src = z;   dst = Az; bid -= 512; }
        else                 { src = znh; dst = Bf; bid -= 1024; }
        int e4 = bid * 256 + tid;
        int m = e4 >> 7, k = (e4 & 127) * 4;
        split4(((const float4*)src)[e4], hb, lb);
        __nv_bfloat16* r = dst + (size_t)m * KP2 + k;
        ST8(r, hb); ST8(r + 512, lb);
    } else if (bid < 1792) {
        // W2 -> Bf rows 1024:1536
        int e4 = (bid - 1536) * 256 + tid;
        int n = e4 >> 7, k = (e4 & 127) * 4;
        split4(((const float4*)W2)[e4], hb, lb);
        __nv_bfloat16* r = Bf + (size_t)(1024 + n) * KP2 + k;
        ST8(r, hb); ST8(r + 512, lb);
    } else if (bid < 1856) {
        // W1[0:512]^T -> Bw1, 64x64 tile transpose
        int t = bid - 1792;
        int tr = t >> 3, tc = t & 7;          // k-tile, n-tile
#pragma unroll
        for (int it = 0; it < 4; it++) {
            int idx = it * 256 + tid;
            int rk = idx >> 4, c4 = idx & 15;
            float4 v = *(const float4*)(W1 + (size_t)(tr * 64 + rk) * ZH + tc * 64 + c4 * 4);
            tile[rk][c4 * 4 + 0] = v.x; tile[rk][c4 * 4 + 1] = v.y;
            tile[rk][c4 * 4 + 2] = v.z; tile[rk][c4 * 4 + 3] = v.w;
        }
        __syncthreads();
#pragma unroll
        for (int it = 0; it < 4; it++) {
            int idx = it * 256 + tid;
            int nr = idx >> 4, k4 = idx & 15;
            float4 v = make_float4(tile[k4 * 4 + 0][nr], tile[k4 * 4 + 1][nr],
                                   tile[k4 * 4 + 2][nr], tile[k4 * 4 + 3][nr]);
            split4(v, hb, lb);
            int k = tr * 64 + k4 * 4;
            __nv_bfloat16* r = Bw1 + (size_t)(tc * 64 + nr) * KP2 + k;
            ST8(r, hb); ST8(r + 512, lb);
        }
    } else if (bid < 1864) {
        // W1[512:576]^T -> Bg
        int t = bid - 1856;                   // n-tile 0..7
#pragma unroll
        for (int it = 0; it < 4; it++) {
            int idx = it * 256 + tid;
            int rk = idx >> 4, c4 = idx & 15;
            float4 v = *(const float4*)(W1 + (size_t)(512 + rk) * ZH + t * 64 + c4 * 4);
            tile[rk][c4 * 4 + 0] = v.x; tile[rk][c4 * 4 + 1] = v.y;
            tile[rk][c4 * 4 + 2] = v.z; tile[rk][c4 * 4 + 3] = v.w;
        }
        __syncthreads();
#pragma unroll
        for (int it = 0; it < 4; it++) {
            int idx = it * 256 + tid;
            int nr = idx >> 4, k4 = idx & 15;
            float4 v = make_float4(tile[k4 * 4 + 0][nr], tile[k4 * 4 + 1][nr],
                                   tile[k4 * 4 + 2][nr], tile[k4 * 4 + 3][nr]);
            split4(v, hb, lb);
            int k = k4 * 4;
            __nv_bfloat16* r = Bg + (size_t)(t * 64 + nr) * KPG2 + k;
            ST8(r, hb); ST8(r + 64, lb);
        }
    } else if (bid < 2120) {
        // ha0 = relu(actions@Wa+ba), split -> Ag
        int idx = (bid - 1864) * 256 + tid;
        int b = idx >> 6, h = idx & 63;
        float s = ba[h];
#pragma unroll
        for (int a = 0; a < ADIM; a++)
            s += actions[b * ADIM + a] * Wa[a * AH + h];
        s = fmaxf(s, 0.f);
        __nv_bfloat16 hi = __float2bfloat16(s);
        __nv_bfloat16 lo = __float2bfloat16(s - __bfloat162float(hi));
        __nv_bfloat16* r = Ag + (size_t)b * KPG2;
        r[h] = hi; r[64 + h] = lo;
    } else {
        // base[b] = (z[b]+b2) . zn[b], 8 rows per block (warp per row)
        int b0 = (bid - 2120) * 8;
        int w = tid >> 5, lane = tid & 31;
        int b = b0 + w;
        const float4* z4 = (const float4*)(z + (size_t)b * ZDIM);
        const float4* zn4 = (const float4*)(zn + (size_t)b * ZDIM);
        const float4* b24 = (const float4*)b2;
        float bp = 0.f;
#pragma unroll
        for (int k4 = lane; k4 < 128; k4 += 32) {
            float4 a = z4[k4], c = zn4[k4], d = b24[k4];
            bp += (a.x + d.x) * c.x + (a.y + d.y) * c.y
                + (a.z + d.z) * c.z + (a.w + d.w) * c.w;
        }
#pragma unroll
        for (int o = 16; o; o >>= 1) bp += __shfl_xor_sync(0xffffffffu, bp, o);
        if (lane == 0) basev[b] = bp;
    }
}

// ---------------- HMMA GEMM: 128x128 tiles, grid 160, 3-stage (R11 config) ---------
#define SM_PITCH 40
#define STAGE_ELEMS (2 * 128 * SM_PITCH)     // A-half + B-half per stage (bf16 elems)
#define MMA_DSMEM (3 * STAGE_ELEMS * 2)      // bytes = 61440

__device__ __forceinline__ void mma16816(float* d, const uint32_t* a, const uint32_t* b) {
    asm volatile(
        "mma.sync.aligned.m16n8k16.row.col.f32.bf16.bf16.f32 "
        "{%0,%1,%2,%3}, {%4,%5,%6,%7}, {%8,%9}, {%0,%1,%2,%3};"
        : "+f"(d[0]), "+f"(d[1]), "+f"(d[2]), "+f"(d[3])
        : "r"(a[0]), "r"(a[1]), "r"(a[2]), "r"(a[3]), "r"(b[0]), "r"(b[1]));
}
__device__ __forceinline__ void cpa16(const void* s, const void* gp) {
    uint32_t sa;
    asm("{ .reg .u64 t; cvta.to.shared.u64 t, %1; cvt.u32.u64 %0, t; }" : "=r"(sa) : "l"(s));
    asm volatile("cp.async.cg.shared.global [%0], [%1], 16;\n" :: "r"(sa), "l"(gp));
}
__device__ __forceinline__ void ldsm4(uint32_t* r, const __nv_bfloat16* p) {
    uint32_t sa;
    asm("{ .reg .u64 t; cvta.to.shared.u64 t, %1; cvt.u32.u64 %0, t; }" : "=r"(sa) : "l"(p));
    asm volatile("ldmatrix.sync.aligned.m8n8.x4.shared.b16 {%0,%1,%2,%3}, [%4];"
                 : "=r"(r[0]), "=r"(r[1]), "=r"(r[2]), "=r"(r[3]) : "r"(sa));
}

__global__ void __launch_bounds__(256, 2)
k_mma(const __nv_bfloat16* __restrict__ Af, const __nv_bfloat16* __restrict__ Az,
      const __nv_bfloat16* __restrict__ Ag, const __nv_bfloat16* __restrict__ Bf,
      const __nv_bfloat16* __restrict__ Bw1, const __nv_bfloat16* __restrict__ Bg,
      const float* __restrict__ b1,
      float* __restrict__ zwb, float* __restrict__ g,
      float* __restrict__ u, float* __restrict__ simmat) {
    extern __shared__ __align__(16) __nv_bfloat16 dsm[];
#define AS(s, r, c) dsm[(s) * STAGE_ELEMS + (r) * SM_PITCH + (c)]
#define BS(s, r, c) dsm[(s) * STAGE_ELEMS + 128 * SM_PITCH + (r) * SM_PITCH + (c)]

    const int tid = threadIdx.x;          // 256
    const int lane = tid & 31, warp = tid >> 5;
    const int grp = lane >> 2, qid = lane & 3;
    const int wm = warp >> 2, wn = warp & 3;   // 2 x 4 warp grid

    const __nv_bfloat16 *Aseg, *Bseg;
    float* Cseg; const float* bias = nullptr;
    int ldk, T, m0, ldc, ccol0, sshift, half;
    {
        int bid = blockIdx.x;
        if (bid < 96) {
            int mt = bid / 12, nt = bid % 12;
            m0 = mt * 128; Aseg = Af; ldk = KP2; T = 48; sshift = 4; half = 512;
            Bseg = Bf + (size_t)nt * 128 * KP2;
            if (nt < 8) { Cseg = simmat; ldc = LDSIM; ccol0 = nt * 128; }
            else        { Cseg = u;      ldc = ZDIM;  ccol0 = (nt - 8) * 128; }
        } else if (bid < 128) {
            int t = bid - 96; int mt = t >> 2, nt = t & 3;
            m0 = mt * 128; Aseg = Az; ldk = KP2; T = 48; sshift = 4; half = 512;
            Bseg = Bw1 + (size_t)nt * 128 * KP2;
            Cseg = zwb; ldc = ZH; ccol0 = nt * 128; bias = b1;
        } else {
            int t = bid - 128; int mt = t >> 2, nt = t & 3;
            m0 = mt * 128; Aseg = Ag; ldk = KPG2; T = 6; sshift = 1; half = 64;
            Bseg = Bg + (size_t)nt * 128 * KPG2;
            Cseg = g; ldc = ZH; ccol0 = nt * 128;
        }
    }

    // ldmatrix lane addressing
    const int arow = wm * 64 + (lane & 7) + ((lane >> 3) & 1) * 8;
    const int akoff = ((lane >> 4) & 1) * 8;
    const int brow = wn * 32 + (lane & 7) + ((lane >> 4) & 1) * 8;
    const int bkoff = ((lane >> 3) & 1) * 8;

    float acc[4][4][4];
#pragma unroll
    for (int i = 0; i < 4; i++)
#pragma unroll
        for (int j = 0; j < 4; j++)
#pragma unroll
            for (int q = 0; q < 4; q++) acc[i][j][q] = 0.f;

    auto load_chunk = [&](int t, int st) {
        int sgm = t >> sshift, tt = t - (sgm << sshift);
        const __nv_bfloat16* Ac = Aseg + (sgm == 2 ? half : 0) + tt * 32;
        const __nv_bfloat16* Bc = Bseg + (sgm == 1 ? half : 0) + tt * 32;
#pragma unroll
        for (int it = 0; it < 2; it++) {
            int idx = it * 256 + tid;
            int row = idx >> 2, sg = (idx & 3) * 8;
            cpa16(&AS(st, row, sg), Ac + (size_t)(m0 + row) * ldk + sg);
        }
#pragma unroll
        for (int it = 0; it < 2; it++) {
            int idx = it * 256 + tid;
            int row = idx >> 2, sg = (idx & 3) * 8;
            cpa16(&BS(st, row, sg), Bc + (size_t)row * ldk + sg);
        }
        asm volatile("cp.async.commit_group;\n" ::: "memory");
    };

    // 3-stage pipeline: preload chunks 0 and 1
    load_chunk(0, 0);
    load_chunk(1, 1);

    for (int t = 0; t < T; t++) {
        const int s = t % 3;
        if (t + 1 < T) asm volatile("cp.async.wait_group 1;\n" ::: "memory");
        else           asm volatile("cp.async.wait_group 0;\n" ::: "memory");
        __syncthreads();
        if (t + 2 < T) load_chunk(t + 2, (t + 2) % 3);

#pragma unroll
        for (int ks = 0; ks < 2; ks++) {
            uint32_t afr[4][4], bt0[4], bt1[4];
            const int akol = ks * 16 + akoff;
            const int bkol = ks * 16 + bkoff;
#pragma unroll
            for (int mi = 0; mi < 4; mi++)
                ldsm4(afr[mi], &AS(s, arow + mi * 16, akol));
            ldsm4(bt0, &BS(s, brow, bkol));
            ldsm4(bt1, &BS(s, brow + 16, bkol));
            uint32_t bfr[4][2] = {{bt0[0], bt0[1]}, {bt0[2], bt0[3]},
                                  {bt1[0], bt1[1]}, {bt1[2], bt1[3]}};
#pragma unroll
            for (int mi = 0; mi < 4; mi++)
#pragma unroll
                for (int ni = 0; ni < 4; ni++)
                    mma16816(acc[mi][ni], afr[mi], bfr[ni]);
        }
    }

#pragma unroll
    for (int mi = 0; mi < 4; mi++) {
        int m = m0 + wm * 64 + mi * 16 + grp;
#pragma unroll
        for (int ni = 0; ni < 4; ni++) {
            int n = ccol0 + wn * 32 + ni * 8 + qid * 2;
            float bx = 0.f, by = 0.f;
            if (bias) { bx = bias[n]; by = bias[n + 1]; }
            *(float2*)&Cseg[(size_t)m * ldc + n] =
                make_float2(acc[mi][ni][0] + bx, acc[mi][ni][1] + by);
            *(float2*)&Cseg[(size_t)(m + 8) * ldc + n] =
                make_float2(acc[mi][ni][2] + bx, acc[mi][ni][3] + by);
        }
    }
#undef AS
#undef BS
}

// ---------------- neg_sim v6: untransposed g staging, float4 inner loop ----------
// Block = 8 b-rows x i-half x k-quarter. grid = 1024.
// gs[row][k] float4-pitch 17 -> conflict-free LDS.128 (banks 4r mod 32 per phase).
// Inner loop per k4: 2 broadcast LDS.128 (zc,uc) + 2 row LDS.128 (g) + 16 fma/alu.
__global__ void __launch_bounds__(256, 5)
k_neg(const float* __restrict__ zwb, const float* __restrict__ g,
      const float* __restrict__ u, float* __restrict__ negp) {
    const int tile  = blockIdx.x >> 3;
    const int ihalf = (blockIdx.x >> 2) & 1;
    const int kq    = blockIdx.x & 3;
    const int b0 = tile * 8;
    const int ibase = 1 + ihalf * 49;        // 1..49 | 50..99
    const int icount = 49 + ihalf;
    const int tid = threadIdx.x, w = tid >> 5, lane = tid & 31;
    const int b = b0 + w;

    __shared__ float4 zc[8][16];
    __shared__ float4 uc[8][16];
    __shared__ float4 gs[71][17];            // valid rows [0,57); 57..70 garbage (predicated off)

    float acc1 = 0.f, acc2 = 0.f;
    const int r1 = w + lane;                 // 0..38, always valid (<57)
    const int r2 = r1 + 32;                  // valid (<57) wherever the result is stored

#pragma unroll 1
    for (int j = 0; j < 2; j++) {
        const int kc4 = kq * 32 + j * 16;    // float4 index of chunk start
        __syncthreads();
        // zwb/u chunk: threads 0-127 -> zc, 128-255 -> uc (8 rows x 16 float4)
        {
            int idx = tid & 127;
            int row = idx >> 4, k4 = idx & 15;
            if (tid < 128) zc[row][k4] = ((const float4*)zwb)[(size_t)(b0 + row) * 128 + kc4 + k4];
            else           uc[row][k4] = ((const float4*)u)[(size_t)(b0 + row) * 128 + kc4 + k4];
        }
        // g chunk: straight copy, 57 rows x 16 float4 (no transpose)
        for (int idx = tid; idx < 57 * 16; idx += 256) {
            int row = idx >> 4, k4 = idx & 15;
            int gr = (b0 + ibase + row) & (BATCH - 1);
            gs[row][k4] = ((const float4*)g)[(size_t)gr * 128 + kc4 + k4];
        }
        __syncthreads();
#pragma unroll
        for (int k4 = 0; k4 < 16; k4++) {
            float4 zv = zc[w][k4];           // warp-broadcast
            float4 uv = uc[w][k4];
            float4 g1 = gs[r1][k4];
            float4 g2 = gs[r2][k4];
            acc1 += fmaxf(zv.x + g1.x, 0.f) * uv.x;
            acc1 += fmaxf(zv.y + g1.y, 0.f) * uv.y;
            acc1 += fmaxf(zv.z + g1.z, 0.f) * uv.z;
            acc1 += fmaxf(zv.w + g1.w, 0.f) * uv.w;
            acc2 += fmaxf(zv.x + g2.x, 0.f) * uv.x;
            acc2 += fmaxf(zv.y + g2.y, 0.f) * uv.y;
            acc2 += fmaxf(zv.z + g2.z, 0.f) * uv.z;
            acc2 += fmaxf(zv.w + g2.w, 0.f) * uv.w;
        }
    }

    float* orow = negp + (size_t)kq * (BATCH * 128) + (size_t)b * 128;
    orow[ibase + lane] = acc1;               // icount >= 32, always valid
    if (lane + 32 < icount)
        orow[ibase + lane + 32] = acc2;
}

// ---------------- per-row softmax + rank count (base precomputed, float4) ----------
__global__ void __launch_bounds__(256)
k_row(const float* __restrict__ simmat, const float* __restrict__ negp,
      const float* __restrict__ basev,
      float* __restrict__ rowlog, int* __restrict__ rowcnt) {
    int b = blockIdx.x;
    int tid = threadIdx.x;   // 256
    const float* row = simmat + (size_t)b * LDSIM;
    const float* pq = negp + (size_t)b * 128;

    const float base = basev[b];
    const float s = row[b];

    float lv[5];
    {
        float4 v4 = ((const float4*)row)[tid];
        lv[0] = v4.x; lv[1] = v4.y; lv[2] = v4.z; lv[3] = v4.w;
    }
    const bool has_neg = (tid < NNEG - 1);
    if (has_neg) {
        int i = tid + 1;
        lv[4] = base + pq[i] + pq[BATCH * 128 + i]
                     + pq[2 * BATCH * 128 + i] + pq[3 * BATCH * 128 + i];
    }
    float mx = lv[0];
#pragma unroll
    for (int q = 1; q < 4; q++) mx = fmaxf(mx, lv[q]);
    if (has_neg) mx = fmaxf(mx, lv[4]);
    float se = 0.f;
#pragma unroll
    for (int q = 0; q < 4; q++) se += __expf((lv[q] - mx) * 10.f);
    if (has_neg) se += __expf((lv[4] - mx) * 10.f);
    int cnt = 0;
    int j0 = tid * 4;
#pragma unroll
    for (int q = 0; q < 4; q++)
        cnt += (lv[q] > s) || (lv[q] == s && (j0 + q) < b);
    if (has_neg) cnt += (lv[4] > s);

#pragma unroll
    for (int o = 16; o; o >>= 1) {
        float om = __shfl_xor_sync(0xffffffffu, mx, o);
        float os = __shfl_xor_sync(0xffffffffu, se, o);
        cnt += __shfl_xor_sync(0xffffffffu, cnt, o);
        float nm = fmaxf(mx, om);
        se = se * __expf((mx - nm) * 10.f) + os * __expf((om - nm) * 10.f);
        mx = nm;
    }
    __shared__ float smx[8], ssm[8];
    __shared__ int scn[8];
    if ((tid & 31) == 0) { smx[tid >> 5] = mx; ssm[tid >> 5] = se; scn[tid >> 5] = cnt; }
    __syncthreads();
    if (tid == 0) {
        float m = smx[0], t = ssm[0]; int c = scn[0];
#pragma unroll
        for (int wv = 1; wv < 8; wv++) {
            float om = smx[wv], os = ssm[wv];
            float nm = fmaxf(m, om);
            t = t * __expf((m - nm) * 10.f) + os * __expf((om - nm) * 10.f);
            m = nm;
            c += scn[wv];
        }
        rowlog[b] = (s - m) * 10.f - logf(t);
        rowcnt[b] = c;
    }
}

// ---------------- final reduction ----------------
__global__ void k_final(const float* __restrict__ rowlog,
                        const int* __restrict__ rowcnt,
                        float* __restrict__ out) {
    int tid = threadIdx.x;  // 1024
    float lg = rowlog[tid];
    int c = rowcnt[tid];
    float a1 = (c < 1) ? 1.f : 0.f;
    float a3 = (c < 3) ? 1.f : 0.f;
    float a10 = (c < 10) ? 1.f : 0.f;

    __shared__ float s0[32], s1[32], s2[32], s3[32];
#pragma unroll
    for (int o = 16; o; o >>= 1) {
        lg  += __shfl_xor_sync(0xffffffffu, lg, o);
        a1  += __shfl_xor_sync(0xffffffffu, a1, o);
        a3  += __shfl_xor_sync(0xffffffffu, a3, o);
        a10 += __shfl_xor_sync(0xffffffffu, a10, o);
    }
    int wid = tid >> 5, lane = tid & 31;
    if (lane == 0) { s0[wid] = lg; s1[wid] = a1; s2[wid] = a3; s3[wid] = a10; }
    __syncthreads();
    if (wid == 0) {
        float v0 = s0[lane], v1 = s1[lane], v2 = s2[lane], v3 = s3[lane];
#pragma unroll
        for (int o = 16; o; o >>= 1) {
            v0 += __shfl_xor_sync(0xffffffffu, v0, o);
            v1 += __shfl_xor_sync(0xffffffffu, v1, o);
            v2 += __shfl_xor_sync(0xffffffffu, v2, o);
            v3 += __shfl_xor_sync(0xffffffffu, v3, o);
        }
        if (lane == 0) {
            out[0] = -v0 / (float)BATCH;
            out[1] = v1 / (float)BATCH;
            out[2] = v2 / (float)BATCH;
            out[3] = v3 / (float)BATCH;
        }
    }
}

// ---------------- launch ----------------
extern "C" void kernel_launch(void* const* d_in, const int* in_sizes, int n_in,
                              void* d_out, int out_size) {
    const float* z          = (const float*)d_in[0];
    const float* z_next     = (const float*)d_in[1];
    const float* z_next_hat = (const float*)d_in[2];
    const float* actions    = (const float*)d_in[3];
    const float* Wa         = (const float*)d_in[4];
    const float* ba         = (const float*)d_in[5];
    const float* W1         = (const float*)d_in[6];
    const float* b1         = (const float*)d_in[7];
    const float* W2         = (const float*)d_in[8];
    const float* b2         = (const float*)d_in[9];
    float* out = (float*)d_out;

    float *g, *zwb, *u, *simmat, *negp, *basev, *rowlog; int* rowcnt;
    __nv_bfloat16 *Af, *Az, *Ag, *Bf, *Bw1, *Bg;
    cudaGetSymbolAddress((void**)&g, d_g);
    cudaGetSymbolAddress((void**)&zwb, d_zwb);
    cudaGetSymbolAddress((void**)&u, d_u);
    cudaGetSymbolAddress((void**)&simmat, d_simmat);
    cudaGetSymbolAddress((void**)&negp, d_negp);
    cudaGetSymbolAddress((void**)&basev, d_base);
    cudaGetSymbolAddress((void**)&rowlog, d_rowlog);
    cudaGetSymbolAddress((void**)&rowcnt, d_rowcnt);
    cudaGetSymbolAddress((void**)&Af, d_Af);
    cudaGetSymbolAddress((void**)&Az, d_Az);
    cudaGetSymbolAddress((void**)&Ag, d_Ag);
    cudaGetSymbolAddress((void**)&Bf, d_Bf);
    cudaGetSymbolAddress((void**)&Bw1, d_Bw1);
    cudaGetSymbolAddress((void**)&Bg, d_Bg);

    cudaFuncSetAttribute(k_mma, cudaFuncAttributeMaxDynamicSharedMemorySize, MMA_DSMEM);

    // 1. conversions + W1 transposes + ha0 + base dots
    k_conv<<<2248, 256>>>(z_next, z, z_next_hat, W2, W1, actions, Wa, ba, b2,
                          Af, Az, Bf, Bw1, Bg, Ag, basev);
    // 2. all GEMMs (sim, u, zwb, g) — grid 160, 3-stage pipeline (R11 config)
    k_mma<<<160, 256, MMA_DSMEM>>>(Af, Az, Ag, Bf, Bw1, Bg, b1, zwb, g, u, simmat);
    // 3. neg_sim k-quarter partials (untransposed float4 staging)
    k_neg<<<1024, 256>>>(zwb, g, u, negp);
    // 4. per-row softmax + rank counts
    k_row<<<BATCH, 256>>>(simmat, negp, basev, rowlog, rowcnt);
    // 5. final outputs
    k_final<<<1, 1024>>>(rowlog, rowcnt, out);
}

// round 15
// speedup vs baseline: 1.2094x; 1.0678x over previous
#include <cuda_runtime.h>
#include <cuda_bf16.h>
#include <math.h>
#include <stdint.h>

// Problem constants
#define BATCH 1024
#define ZDIM  512
#define ADIM  8
#define AH    64
#define ZH    512
#define NNEG  100
#define NCOLS 1123
#define LDSIM 1152

// split-bf16 storage: [hi | lo], segment-walked 3x in the GEMM
#define KP2   1024          // 2*512
#define KPG2  128           // 2*64

// ---------------- device scratch ----------------
__device__ float d_g[BATCH * ZH];
__device__ float d_zwb[BATCH * ZH];
__device__ float d_u[BATCH * ZDIM];
__device__ float d_simmat[BATCH * LDSIM];
__device__ float d_negp[4][BATCH * 128];      // k-quarter partials of neg_sim
__device__ float d_base[BATCH];               // (z[b]+b2).zn[b]
__device__ float d_rowlog[BATCH];
__device__ int   d_rowcnt[BATCH];

__device__ __nv_bfloat16 d_Af[BATCH * KP2];    // z_next'  [h|l]
__device__ __nv_bfloat16 d_Az[BATCH * KP2];    // z'
__device__ __nv_bfloat16 d_Ag[BATCH * KPG2];   // ha0'
__device__ __nv_bfloat16 d_Bf[1536 * KP2];     // rows 0:1024 znh', 1024:1536 W2'
__device__ __nv_bfloat16 d_Bw1[512 * KP2];     // W1[0:512]^T'
__device__ __nv_bfloat16 d_Bg[512 * KPG2];     // W1[512:576]^T'

// ---------------- split helper ----------------
__device__ __forceinline__ void split4(float4 v, __nv_bfloat16* hb, __nv_bfloat16* lb) {
    const float* c = &v.x;
#pragma unroll
    for (int j = 0; j < 4; j++) {
        __nv_bfloat16 h = __float2bfloat16(c[j]);
        hb[j] = h;
        lb[j] = __float2bfloat16(c[j] - __bfloat162float(h));
    }
}
#define ST8(p, a) (*reinterpret_cast<uint2*>(p) = *reinterpret_cast<const uint2*>(a))

// ---------------- conversions + ha0 + base, one launch, grid 2248 ----------------
__global__ void __launch_bounds__(256)
k_conv(const float* __restrict__ zn, const float* __restrict__ z,
       const float* __restrict__ znh, const float* __restrict__ W2,
       const float* __restrict__ W1,
       const float* __restrict__ actions, const float* __restrict__ Wa,
       const float* __restrict__ ba, const float* __restrict__ b2,
       __nv_bfloat16* __restrict__ Af, __nv_bfloat16* __restrict__ Az,
       __nv_bfloat16* __restrict__ Bf, __nv_bfloat16* __restrict__ Bw1,
       __nv_bfloat16* __restrict__ Bg, __nv_bfloat16* __restrict__ Ag,
       float* __restrict__ basev) {
    __shared__ float tile[64][65];
    int bid = blockIdx.x, tid = threadIdx.x;
    __align__(8) __nv_bfloat16 hb[4], lb[4];

    if (bid < 1536) {
        // element-wise: Af <- z_next | Az <- z | Bf[0:1024] <- znh
        const float* src; __nv_bfloat16* dst;
        if (bid < 512)       { src = zn;  dst = Af; }
        else if (bid < 1024) { src = z;   dst = Az; bid -= 512; }
        else                 { src = znh; dst = Bf; bid -= 1024; }
        int e4 = bid * 256 + tid;
        int m = e4 >> 7, k = (e4 & 127) * 4;
        split4(((const float4*)src)[e4], hb, lb);
        __nv_bfloat16* r = dst + (size_t)m * KP2 + k;
        ST8(r, hb); ST8(r + 512, lb);
    } else if (bid < 1792) {
        // W2 -> Bf rows 1024:1536
        int e4 = (bid - 1536) * 256 + tid;
        int n = e4 >> 7, k = (e4 & 127) * 4;
        split4(((const float4*)W2)[e4], hb, lb);
        __nv_bfloat16* r = Bf + (size_t)(1024 + n) * KP2 + k;
        ST8(r, hb); ST8(r + 512, lb);
    } else if (bid < 1856) {
        // W1[0:512]^T -> Bw1, 64x64 tile transpose
        int t = bid - 1792;
        int tr = t >> 3, tc = t & 7;          // k-tile, n-tile
#pragma unroll
        for (int it = 0; it < 4; it++) {
            int idx = it * 256 + tid;
            int rk = idx >> 4, c4 = idx & 15;
            float4 v = *(const float4*)(W1 + (size_t)(tr * 64 + rk) * ZH + tc * 64 + c4 * 4);
            tile[rk][c4 * 4 + 0] = v.x; tile[rk][c4 * 4 + 1] = v.y;
            tile[rk][c4 * 4 + 2] = v.z; tile[rk][c4 * 4 + 3] = v.w;
        }
        __syncthreads();
#pragma unroll
        for (int it = 0; it < 4; it++) {
            int idx = it * 256 + tid;
            int nr = idx >> 4, k4 = idx & 15;
            float4 v = make_float4(tile[k4 * 4 + 0][nr], tile[k4 * 4 + 1][nr],
                                   tile[k4 * 4 + 2][nr], tile[k4 * 4 + 3][nr]);
            split4(v, hb, lb);
            int k = tr * 64 + k4 * 4;
            __nv_bfloat16* r = Bw1 + (size_t)(tc * 64 + nr) * KP2 + k;
            ST8(r, hb); ST8(r + 512, lb);
        }
    } else if (bid < 1864) {
        // W1[512:576]^T -> Bg
        int t = bid - 1856;                   // n-tile 0..7
#pragma unroll
        for (int it = 0; it < 4; it++) {
            int idx = it * 256 + tid;
            int rk = idx >> 4, c4 = idx & 15;
            float4 v = *(const float4*)(W1 + (size_t)(512 + rk) * ZH + t * 64 + c4 * 4);
            tile[rk][c4 * 4 + 0] = v.x; tile[rk][c4 * 4 + 1] = v.y;
            tile[rk][c4 * 4 + 2] = v.z; tile[rk][c4 * 4 + 3] = v.w;
        }
        __syncthreads();
#pragma unroll
        for (int it = 0; it < 4; it++) {
            int idx = it * 256 + tid;
            int nr = idx >> 4, k4 = idx & 15;
            float4 v = make_float4(tile[k4 * 4 + 0][nr], tile[k4 * 4 + 1][nr],
                                   tile[k4 * 4 + 2][nr], tile[k4 * 4 + 3][nr]);
            split4(v, hb, lb);
            int k = k4 * 4;
            __nv_bfloat16* r = Bg + (size_t)(t * 64 + nr) * KPG2 + k;
            ST8(r, hb); ST8(r + 64, lb);
        }
    } else if (bid < 2120) {
        // ha0 = relu(actions@Wa+ba), split -> Ag
        int idx = (bid - 1864) * 256 + tid;
        int b = idx >> 6, h = idx & 63;
        float s = ba[h];
#pragma unroll
        for (int a = 0; a < ADIM; a++)
            s += actions[b * ADIM + a] * Wa[a * AH + h];
        s = fmaxf(s, 0.f);
        __nv_bfloat16 hi = __float2bfloat16(s);
        __nv_bfloat16 lo = __float2bfloat16(s - __bfloat162float(hi));
        __nv_bfloat16* r = Ag + (size_t)b * KPG2;
        r[h] = hi; r[64 + h] = lo;
    } else {
        // base[b] = (z[b]+b2) . zn[b], 8 rows per block (warp per row)
        int b0 = (bid - 2120) * 8;
        int w = tid >> 5, lane = tid & 31;
        int b = b0 + w;
        const float4* z4 = (const float4*)(z + (size_t)b * ZDIM);
        const float4* zn4 = (const float4*)(zn + (size_t)b * ZDIM);
        const float4* b24 = (const float4*)b2;
        float bp = 0.f;
#pragma unroll
        for (int k4 = lane; k4 < 128; k4 += 32) {
            float4 a = z4[k4], c = zn4[k4], d = b24[k4];
            bp += (a.x + d.x) * c.x + (a.y + d.y) * c.y
                + (a.z + d.z) * c.z + (a.w + d.w) * c.w;
        }
#pragma unroll
        for (int o = 16; o; o >>= 1) bp += __shfl_xor_sync(0xffffffffu, bp, o);
        if (lane == 0) basev[b] = bp;
    }
}

// ---------------- HMMA GEMM: 128x128 tiles, BK=64, 2-stage, grid 160 ---------------
// Half the chunk count of BK=32 -> half the barrier/wait events.
#define SM_PITCH 72                           // 64 k + 8 pad (144B rows, ldmatrix-clean)
#define STAGE_ELEMS (2 * 128 * SM_PITCH)      // A + B per stage (bf16 elems)
#define MMA_DSMEM (2 * STAGE_ELEMS * 2)       // 73728 bytes

__device__ __forceinline__ void mma16816(float* d, const uint32_t* a, const uint32_t* b) {
    asm volatile(
        "mma.sync.aligned.m16n8k16.row.col.f32.bf16.bf16.f32 "
        "{%0,%1,%2,%3}, {%4,%5,%6,%7}, {%8,%9}, {%0,%1,%2,%3};"
        : "+f"(d[0]), "+f"(d[1]), "+f"(d[2]), "+f"(d[3])
        : "r"(a[0]), "r"(a[1]), "r"(a[2]), "r"(a[3]), "r"(b[0]), "r"(b[1]));
}
__device__ __forceinline__ void cpa16(const void* s, const void* gp) {
    uint32_t sa;
    asm("{ .reg .u64 t; cvta.to.shared.u64 t, %1; cvt.u32.u64 %0, t; }" : "=r"(sa) : "l"(s));
    asm volatile("cp.async.cg.shared.global [%0], [%1], 16;\n" :: "r"(sa), "l"(gp));
}
__device__ __forceinline__ void ldsm4(uint32_t* r, const __nv_bfloat16* p) {
    uint32_t sa;
    asm("{ .reg .u64 t; cvta.to.shared.u64 t, %1; cvt.u32.u64 %0, t; }" : "=r"(sa) : "l"(p));
    asm volatile("ldmatrix.sync.aligned.m8n8.x4.shared.b16 {%0,%1,%2,%3}, [%4];"
                 : "=r"(r[0]), "=r"(r[1]), "=r"(r[2]), "=r"(r[3]) : "r"(sa));
}

__global__ void __launch_bounds__(256, 2)
k_mma(const __nv_bfloat16* __restrict__ Af, const __nv_bfloat16* __restrict__ Az,
      const __nv_bfloat16* __restrict__ Ag, const __nv_bfloat16* __restrict__ Bf,
      const __nv_bfloat16* __restrict__ Bw1, const __nv_bfloat16* __restrict__ Bg,
      const float* __restrict__ b1,
      float* __restrict__ zwb, float* __restrict__ g,
      float* __restrict__ u, float* __restrict__ simmat) {
    extern __shared__ __align__(16) __nv_bfloat16 dsm[];
#define AS(s, r, c) dsm[(s) * STAGE_ELEMS + (r) * SM_PITCH + (c)]
#define BS(s, r, c) dsm[(s) * STAGE_ELEMS + 128 * SM_PITCH + (r) * SM_PITCH + (c)]

    const int tid = threadIdx.x;          // 256
    const int lane = tid & 31, warp = tid >> 5;
    const int grp = lane >> 2, qid = lane & 3;
    const int wm = warp >> 2, wn = warp & 3;   // 2 x 4 warp grid

    const __nv_bfloat16 *Aseg, *Bseg;
    float* Cseg; const float* bias = nullptr;
    int ldk, T, m0, ldc, ccol0, sshift, half;
    {
        int bid = blockIdx.x;
        if (bid < 96) {
            int mt = bid / 12, nt = bid % 12;
            m0 = mt * 128; Aseg = Af; ldk = KP2; T = 24; sshift = 3; half = 512;
            Bseg = Bf + (size_t)nt * 128 * KP2;
            if (nt < 8) { Cseg = simmat; ldc = LDSIM; ccol0 = nt * 128; }
            else        { Cseg = u;      ldc = ZDIM;  ccol0 = (nt - 8) * 128; }
        } else if (bid < 128) {
            int t = bid - 96; int mt = t >> 2, nt = t & 3;
            m0 = mt * 128; Aseg = Az; ldk = KP2; T = 24; sshift = 3; half = 512;
            Bseg = Bw1 + (size_t)nt * 128 * KP2;
            Cseg = zwb; ldc = ZH; ccol0 = nt * 128; bias = b1;
        } else {
            int t = bid - 128; int mt = t >> 2, nt = t & 3;
            m0 = mt * 128; Aseg = Ag; ldk = KPG2; T = 3; sshift = 0; half = 64;
            Bseg = Bg + (size_t)nt * 128 * KPG2;
            Cseg = g; ldc = ZH; ccol0 = nt * 128;
        }
    }

    // ldmatrix lane addressing
    const int arow = wm * 64 + (lane & 7) + ((lane >> 3) & 1) * 8;
    const int akoff = ((lane >> 4) & 1) * 8;
    const int brow = wn * 32 + (lane & 7) + ((lane >> 4) & 1) * 8;
    const int bkoff = ((lane >> 3) & 1) * 8;

    float acc[4][4][4];
#pragma unroll
    for (int i = 0; i < 4; i++)
#pragma unroll
        for (int j = 0; j < 4; j++)
#pragma unroll
            for (int q = 0; q < 4; q++) acc[i][j][q] = 0.f;

    // chunk = 64 k columns. segment walk: (Ah,Bh),(Ah,Bl),(Al,Bh)
    auto load_chunk = [&](int t, int st) {
        int sgm = t >> sshift, tt = t - (sgm << sshift);
        const __nv_bfloat16* Ac = Aseg + (sgm == 2 ? half : 0) + tt * 64;
        const __nv_bfloat16* Bc = Bseg + (sgm == 1 ? half : 0) + tt * 64;
#pragma unroll
        for (int it = 0; it < 4; it++) {      // A: 128 rows x 64 k = 1024 x 16B
            int idx = it * 256 + tid;
            int row = idx >> 3, sg = (idx & 7) * 8;
            cpa16(&AS(st, row, sg), Ac + (size_t)(m0 + row) * ldk + sg);
        }
#pragma unroll
        for (int it = 0; it < 4; it++) {      // B: 128 rows x 64 k
            int idx = it * 256 + tid;
            int row = idx >> 3, sg = (idx & 7) * 8;
            cpa16(&BS(st, row, sg), Bc + (size_t)row * ldk + sg);
        }
        asm volatile("cp.async.commit_group;\n" ::: "memory");
    };

    load_chunk(0, 0);

    for (int t = 0; t < T; t++) {
        const int s = t & 1;
        if (t + 1 < T) load_chunk(t + 1, 1 - s);
        if (t + 1 < T) asm volatile("cp.async.wait_group 1;\n" ::: "memory");
        else           asm volatile("cp.async.wait_group 0;\n" ::: "memory");
        __syncthreads();

#pragma unroll
        for (int ks = 0; ks < 4; ks++) {
            uint32_t afr[4][4], bt0[4], bt1[4];
            const int akol = ks * 16 + akoff;
            const int bkol = ks * 16 + bkoff;
#pragma unroll
            for (int mi = 0; mi < 4; mi++)
                ldsm4(afr[mi], &AS(s, arow + mi * 16, akol));
            ldsm4(bt0, &BS(s, brow, bkol));
            ldsm4(bt1, &BS(s, brow + 16, bkol));
            uint32_t bfr[4][2] = {{bt0[0], bt0[1]}, {bt0[2], bt0[3]},
                                  {bt1[0], bt1[1]}, {bt1[2], bt1[3]}};
#pragma unroll
            for (int mi = 0; mi < 4; mi++)
#pragma unroll
                for (int ni = 0; ni < 4; ni++)
                    mma16816(acc[mi][ni], afr[mi], bfr[ni]);
        }
        __syncthreads();
    }

#pragma unroll
    for (int mi = 0; mi < 4; mi++) {
        int m = m0 + wm * 64 + mi * 16 + grp;
#pragma unroll
        for (int ni = 0; ni < 4; ni++) {
            int n = ccol0 + wn * 32 + ni * 8 + qid * 2;
            float bx = 0.f, by = 0.f;
            if (bias) { bx = bias[n]; by = bias[n + 1]; }
            *(float2*)&Cseg[(size_t)m * ldc + n] =
                make_float2(acc[mi][ni][0] + bx, acc[mi][ni][1] + by);
            *(float2*)&Cseg[(size_t)(m + 8) * ldc + n] =
                make_float2(acc[mi][ni][2] + bx, acc[mi][ni][3] + by);
        }
    }
#undef AS
#undef BS
}

// ---------------- neg_sim v6: untransposed g staging, float4 inner loop ----------
__global__ void __launch_bounds__(256, 5)
k_neg(const float* __restrict__ zwb, const float* __restrict__ g,
      const float* __restrict__ u, float* __restrict__ negp) {
    const int tile  = blockIdx.x >> 3;
    const int ihalf = (blockIdx.x >> 2) & 1;
    const int kq    = blockIdx.x & 3;
    const int b0 = tile * 8;
    const int ibase = 1 + ihalf * 49;        // 1..49 | 50..99
    const int icount = 49 + ihalf;
    const int tid = threadIdx.x, w = tid >> 5, lane = tid & 31;
    const int b = b0 + w;

    __shared__ float4 zc[8][16];
    __shared__ float4 uc[8][16];
    __shared__ float4 gs[71][17];            // valid rows [0,57)

    float acc1 = 0.f, acc2 = 0.f;
    const int r1 = w + lane;
    const int r2 = r1 + 32;

#pragma unroll 1
    for (int j = 0; j < 2; j++) {
        const int kc4 = kq * 32 + j * 16;
        __syncthreads();
        {
            int idx = tid & 127;
            int row = idx >> 4, k4 = idx & 15;
            if (tid < 128) zc[row][k4] = ((const float4*)zwb)[(size_t)(b0 + row) * 128 + kc4 + k4];
            else           uc[row][k4] = ((const float4*)u)[(size_t)(b0 + row) * 128 + kc4 + k4];
        }
        for (int idx = tid; idx < 57 * 16; idx += 256) {
            int row = idx >> 4, k4 = idx & 15;
            int gr = (b0 + ibase + row) & (BATCH - 1);
            gs[row][k4] = ((const float4*)g)[(size_t)gr * 128 + kc4 + k4];
        }
        __syncthreads();
#pragma unroll
        for (int k4 = 0; k4 < 16; k4++) {
            float4 zv = zc[w][k4];
            float4 uv = uc[w][k4];
            float4 g1 = gs[r1][k4];
            float4 g2 = gs[r2][k4];
            acc1 += fmaxf(zv.x + g1.x, 0.f) * uv.x;
            acc1 += fmaxf(zv.y + g1.y, 0.f) * uv.y;
            acc1 += fmaxf(zv.z + g1.z, 0.f) * uv.z;
            acc1 += fmaxf(zv.w + g1.w, 0.f) * uv.w;
            acc2 += fmaxf(zv.x + g2.x, 0.f) * uv.x;
            acc2 += fmaxf(zv.y + g2.y, 0.f) * uv.y;
            acc2 += fmaxf(zv.z + g2.z, 0.f) * uv.z;
            acc2 += fmaxf(zv.w + g2.w, 0.f) * uv.w;
        }
    }

    float* orow = negp + (size_t)kq * (BATCH * 128) + (size_t)b * 128;
    orow[ibase + lane] = acc1;
    if (lane + 32 < icount)
        orow[ibase + lane + 32] = acc2;
}

// ---------------- per-row softmax + rank count (base precomputed, float4) ----------
__global__ void __launch_bounds__(256)
k_row(const float* __restrict__ simmat, const float* __restrict__ negp,
      const float* __restrict__ basev,
      float* __restrict__ rowlog, int* __restrict__ rowcnt) {
    int b = blockIdx.x;
    int tid = threadIdx.x;   // 256
    const float* row = simmat + (size_t)b * LDSIM;
    const float* pq = negp + (size_t)b * 128;

    const float base = basev[b];
    const float s = row[b];

    float lv[5];
    {
        float4 v4 = ((const float4*)row)[tid];
        lv[0] = v4.x; lv[1] = v4.y; lv[2] = v4.z; lv[3] = v4.w;
    }
    const bool has_neg = (tid < NNEG - 1);
    if (has_neg) {
        int i = tid + 1;
        lv[4] = base + pq[i] + pq[BATCH * 128 + i]
                     + pq[2 * BATCH * 128 + i] + pq[3 * BATCH * 128 + i];
    }
    float mx = lv[0];
#pragma unroll
    for (int q = 1; q < 4; q++) mx = fmaxf(mx, lv[q]);
    if (has_neg) mx = fmaxf(mx, lv[4]);
    float se = 0.f;
#pragma unroll
    for (int q = 0; q < 4; q++) se += __expf((lv[q] - mx) * 10.f);
    if (has_neg) se += __expf((lv[4] - mx) * 10.f);
    int cnt = 0;
    int j0 = tid * 4;
#pragma unroll
    for (int q = 0; q < 4; q++)
        cnt += (lv[q] > s) || (lv[q] == s && (j0 + q) < b);
    if (has_neg) cnt += (lv[4] > s);

#pragma unroll
    for (int o = 16; o; o >>= 1) {
        float om = __shfl_xor_sync(0xffffffffu, mx, o);
        float os = __shfl_xor_sync(0xffffffffu, se, o);
        cnt += __shfl_xor_sync(0xffffffffu, cnt, o);
        float nm = fmaxf(mx, om);
        se = se * __expf((mx - nm) * 10.f) + os * __expf((om - nm) * 10.f);
        mx = nm;
    }
    __shared__ float smx[8], ssm[8];
    __shared__ int scn[8];
    if ((tid & 31) == 0) { smx[tid >> 5] = mx; ssm[tid >> 5] = se; scn[tid >> 5] = cnt; }
    __syncthreads();
    if (tid == 0) {
        float m = smx[0], t = ssm[0]; int c = scn[0];
#pragma unroll
        for (int wv = 1; wv < 8; wv++) {
            float om = smx[wv], os = ssm[wv];
            float nm = fmaxf(m, om);
            t = t * __expf((m - nm) * 10.f) + os * __expf((om - nm) * 10.f);
            m = nm;
            c += scn[wv];
        }
        rowlog[b] = (s - m) * 10.f - logf(t);
        rowcnt[b] = c;
    }
}

// ---------------- final reduction ----------------
__global__ void k_final(const float* __restrict__ rowlog,
                        const int* __restrict__ rowcnt,
                        float* __restrict__ out) {
    int tid = threadIdx.x;  // 1024
    float lg = rowlog[tid];
    int c = rowcnt[tid];
    float a1 = (c < 1) ? 1.f : 0.f;
    float a3 = (c < 3) ? 1.f : 0.f;
    float a10 = (c < 10) ? 1.f : 0.f;

    __shared__ float s0[32], s1[32], s2[32], s3[32];
#pragma unroll
    for (int o = 16; o; o >>= 1) {
        lg  += __shfl_xor_sync(0xffffffffu, lg, o);
        a1  += __shfl_xor_sync(0xffffffffu, a1, o);
        a3  += __shfl_xor_sync(0xffffffffu, a3, o);
        a10 += __shfl_xor_sync(0xffffffffu, a10, o);
    }
    int wid = tid >> 5, lane = tid & 31;
    if (lane == 0) { s0[wid] = lg; s1[wid] = a1; s2[wid] = a3; s3[wid] = a10; }
    __syncthreads();
    if (wid == 0) {
        float v0 = s0[lane], v1 = s1[lane], v2 = s2[lane], v3 = s3[lane];
#pragma unroll
        for (int o = 16; o; o >>= 1) {
            v0 += __shfl_xor_sync(0xffffffffu, v0, o);
            v1 += __shfl_xor_sync(0xffffffffu, v1, o);
            v2 += __shfl_xor_sync(0xffffffffu, v2, o);
            v3 += __shfl_xor_sync(0xffffffffu, v3, o);
        }
        if (lane == 0) {
            out[0] = -v0 / (float)BATCH;
            out[1] = v1 / (float)BATCH;
            out[2] = v2 / (float)BATCH;
            out[3] = v3 / (float)BATCH;
        }
    }
}

// ---------------- launch ----------------
extern "C" void kernel_launch(void* const* d_in, const int* in_sizes, int n_in,
                              void* d_out, int out_size) {
    const float* z          = (const float*)d_in[0];
    const float* z_next     = (const float*)d_in[1];
    const float* z_next_hat = (const float*)d_in[2];
    const float* actions    = (const float*)d_in[3];
    const float* Wa         = (const float*)d_in[4];
    const float* ba         = (const float*)d_in[5];
    const float* W1         = (const float*)d_in[6];
    const float* b1         = (const float*)d_in[7];
    const float* W2         = (const float*)d_in[8];
    const float* b2         = (const float*)d_in[9];
    float* out = (float*)d_out;

    float *g, *zwb, *u, *simmat, *negp, *basev, *rowlog; int* rowcnt;
    __nv_bfloat16 *Af, *Az, *Ag, *Bf, *Bw1, *Bg;
    cudaGetSymbolAddress((void**)&g, d_g);
    cudaGetSymbolAddress((void**)&zwb, d_zwb);
    cudaGetSymbolAddress((void**)&u, d_u);
    cudaGetSymbolAddress((void**)&simmat, d_simmat);
    cudaGetSymbolAddress((void**)&negp, d_negp);
    cudaGetSymbolAddress((void**)&basev, d_base);
    cudaGetSymbolAddress((void**)&rowlog, d_rowlog);
    cudaGetSymbolAddress((void**)&rowcnt, d_rowcnt);
    cudaGetSymbolAddress((void**)&Af, d_Af);
    cudaGetSymbolAddress((void**)&Az, d_Az);
    cudaGetSymbolAddress((void**)&Ag, d_Ag);
    cudaGetSymbolAddress((void**)&Bf, d_Bf);
    cudaGetSymbolAddress((void**)&Bw1, d_Bw1);
    cudaGetSymbolAddress((void**)&Bg, d_Bg);

    cudaFuncSetAttribute(k_mma, cudaFuncAttributeMaxDynamicSharedMemorySize, MMA_DSMEM);

    // 1. conversions + W1 transposes + ha0 + base dots
    k_conv<<<2248, 256>>>(z_next, z, z_next_hat, W2, W1, actions, Wa, ba, b2,
                          Af, Az, Bf, Bw1, Bg, Ag, basev);
    // 2. all GEMMs (sim, u, zwb, g) — BK=64, 2-stage, grid 160
    k_mma<<<160, 256, MMA_DSMEM>>>(Af, Az, Ag, Bf, Bw1, Bg, b1, zwb, g, u, simmat);
    // 3. neg_sim k-quarter partials (untransposed float4 staging)
    k_neg<<<1024, 256>>>(zwb, g, u, negp);
    // 4. per-row softmax + rank counts
    k_row<<<BATCH, 256>>>(simmat, negp, basev, rowlog, rowcnt);
    // 5. final outputs
    k_final<<<1, 1024>>>(rowlog, rowcnt, out);
}